// round 1
// baseline (speedup 1.0000x reference)
#include <cuda_runtime.h>
#include <math.h>
#include <stdint.h>

// ---------------------------------------------------------------------------
// SSITrimLoss: masked scale/shift-invariant trimmed L1 loss.
//   per sample: alpha,beta from masked least squares; res=|alpha*p+beta-g|;
//   keep k=floor(0.8*n) smallest residuals (invalid -> BIG), mean them.
// Strategy: moments pass -> residual pass (+L0 hist) -> radix-select (3 levels
// of 11/11/10 bits over float bits, exact) -> sum/count below threshold.
// ---------------------------------------------------------------------------

#define BB    32
#define NMAX  491520
#define TPB   256
#define BLKX  16
#define BIGF  1e30f

__device__ __align__(16) float g_res[(size_t)BB * NMAX];
__device__ unsigned int       g_hist[BB][2048];
__device__ double             g_mom[BB][5];     // n, sp, sg, spp, spg
__device__ float              g_alpha[BB], g_beta[BB];
__device__ int                g_k[BB];
__device__ long long          g_rank[BB];
__device__ unsigned int       g_prefix[BB];
__device__ double             g_sumless[BB];
__device__ unsigned long long g_cntless[BB];

// ----------------------------- init ---------------------------------------
__global__ void init_kernel() {
    int i = blockIdx.x * blockDim.x + threadIdx.x;
    if (i < BB * 2048) ((unsigned int*)g_hist)[i] = 0u;
    if (i < BB * 5)    ((double*)g_mom)[i] = 0.0;
    if (i < BB) {
        g_sumless[i] = 0.0;
        g_cntless[i] = 0ull;
    }
}

// ------------------------- block reduce helpers ----------------------------
__device__ __forceinline__ float warp_sum(float v) {
    #pragma unroll
    for (int off = 16; off; off >>= 1) v += __shfl_down_sync(0xffffffffu, v, off);
    return v;
}
__device__ __forceinline__ long long warp_sum_ll(long long v) {
    #pragma unroll
    for (int off = 16; off; off >>= 1) v += __shfl_down_sync(0xffffffffu, v, off);
    return v;
}

// ----------------------------- moments ------------------------------------
__global__ void moments_kernel(const float* __restrict__ pred,
                               const float* __restrict__ gt,
                               const int* __restrict__ mask, int N) {
    int b = blockIdx.y;
    int n4 = N >> 2;
    const float4* p4 = reinterpret_cast<const float4*>(pred) + (size_t)b * n4;
    const float4* g4 = reinterpret_cast<const float4*>(gt)   + (size_t)b * n4;
    const int4*   m4 = reinterpret_cast<const int4*>(mask)   + (size_t)b * n4;

    float sn = 0.f, sp = 0.f, sg = 0.f, spp = 0.f, spg = 0.f;
    int stride = gridDim.x * blockDim.x;
    for (int i = blockIdx.x * blockDim.x + threadIdx.x; i < n4; i += stride) {
        float4 p = p4[i]; float4 g = g4[i]; int4 m = m4[i];
        {
            float mf = m.x > 0 ? 1.f : 0.f;
            sn += mf; sp += mf * p.x; sg += mf * g.x;
            spp += mf * p.x * p.x; spg += mf * p.x * g.x;
        }
        {
            float mf = m.y > 0 ? 1.f : 0.f;
            sn += mf; sp += mf * p.y; sg += mf * g.y;
            spp += mf * p.y * p.y; spg += mf * p.y * g.y;
        }
        {
            float mf = m.z > 0 ? 1.f : 0.f;
            sn += mf; sp += mf * p.z; sg += mf * g.z;
            spp += mf * p.z * p.z; spg += mf * p.z * g.z;
        }
        {
            float mf = m.w > 0 ? 1.f : 0.f;
            sn += mf; sp += mf * p.w; sg += mf * g.w;
            spp += mf * p.w * p.w; spg += mf * p.w * g.w;
        }
    }

    sn = warp_sum(sn); sp = warp_sum(sp); sg = warp_sum(sg);
    spp = warp_sum(spp); spg = warp_sum(spg);

    __shared__ float ws[5][8];
    int lane = threadIdx.x & 31, w = threadIdx.x >> 5;
    if (lane == 0) { ws[0][w]=sn; ws[1][w]=sp; ws[2][w]=sg; ws[3][w]=spp; ws[4][w]=spg; }
    __syncthreads();
    if (w == 0) {
        float a0 = lane < 8 ? ws[0][lane] : 0.f;
        float a1 = lane < 8 ? ws[1][lane] : 0.f;
        float a2 = lane < 8 ? ws[2][lane] : 0.f;
        float a3 = lane < 8 ? ws[3][lane] : 0.f;
        float a4 = lane < 8 ? ws[4][lane] : 0.f;
        a0 = warp_sum(a0); a1 = warp_sum(a1); a2 = warp_sum(a2);
        a3 = warp_sum(a3); a4 = warp_sum(a4);
        if (lane == 0) {
            atomicAdd(&g_mom[b][0], (double)a0);
            atomicAdd(&g_mom[b][1], (double)a1);
            atomicAdd(&g_mom[b][2], (double)a2);
            atomicAdd(&g_mom[b][3], (double)a3);
            atomicAdd(&g_mom[b][4], (double)a4);
        }
    }
}

// --------------------------- alpha/beta/k ----------------------------------
__global__ void finalize_moments_kernel() {
    int b = threadIdx.x;
    if (b >= BB) return;
    double n  = g_mom[b][0];
    double ns = n < 1.0 ? 1.0 : n;
    double md = g_mom[b][1] / ns;
    double mz = g_mom[b][2] / ns;
    double var = g_mom[b][3] / ns - md * md;
    double cov = g_mom[b][4] / ns - md * mz;
    double alpha = cov / (var + 1e-6);
    double beta  = mz - alpha * md;
    g_alpha[b] = (float)alpha;
    g_beta[b]  = (float)beta;
    int k = (int)floorf((1.0f - 0.2f) * (float)n);   // match f32 reference arith
    g_k[b] = k;
    g_rank[b] = (long long)k - 1;
    g_prefix[b] = 0u;
}

// ------------------- residuals + level-0 histogram --------------------------
__global__ void residual_kernel(const float* __restrict__ pred,
                                const float* __restrict__ gt,
                                const int* __restrict__ mask, int N) {
    int b = blockIdx.y;
    __shared__ unsigned int sh[2048];
    for (int i = threadIdx.x; i < 2048; i += blockDim.x) sh[i] = 0u;
    __syncthreads();

    int n4 = N >> 2;
    const float4* p4 = reinterpret_cast<const float4*>(pred) + (size_t)b * n4;
    const float4* g4 = reinterpret_cast<const float4*>(gt)   + (size_t)b * n4;
    const int4*   m4 = reinterpret_cast<const int4*>(mask)   + (size_t)b * n4;
    float4*       r4 = reinterpret_cast<float4*>(g_res)      + (size_t)b * n4;

    float a = g_alpha[b], be = g_beta[b];
    int stride = gridDim.x * blockDim.x;
    for (int i = blockIdx.x * blockDim.x + threadIdx.x; i < n4; i += stride) {
        float4 p = p4[i]; float4 g = g4[i]; int4 m = m4[i];
        float4 r;
        r.x = (m.x > 0) ? fabsf(fmaf(a, p.x, be) - g.x) : BIGF;
        r.y = (m.y > 0) ? fabsf(fmaf(a, p.y, be) - g.y) : BIGF;
        r.z = (m.z > 0) ? fabsf(fmaf(a, p.z, be) - g.z) : BIGF;
        r.w = (m.w > 0) ? fabsf(fmaf(a, p.w, be) - g.w) : BIGF;
        r4[i] = r;
        atomicAdd(&sh[__float_as_uint(r.x) >> 21], 1u);
        atomicAdd(&sh[__float_as_uint(r.y) >> 21], 1u);
        atomicAdd(&sh[__float_as_uint(r.z) >> 21], 1u);
        atomicAdd(&sh[__float_as_uint(r.w) >> 21], 1u);
    }
    __syncthreads();
    for (int i = threadIdx.x; i < 2048; i += blockDim.x)
        if (sh[i]) atomicAdd(&g_hist[b][i], sh[i]);
}

// ---------------- histogram for deeper radix levels -------------------------
__global__ void hist_kernel(int N, int matchShift, int binShift, unsigned int binMask) {
    int b = blockIdx.y;
    unsigned int pref = g_prefix[b];
    __shared__ unsigned int sh[2048];
    for (int i = threadIdx.x; i < 2048; i += blockDim.x) sh[i] = 0u;
    __syncthreads();

    int n4 = N >> 2;
    const float4* r4 = reinterpret_cast<const float4*>(g_res) + (size_t)b * n4;
    int stride = gridDim.x * blockDim.x;
    for (int i = blockIdx.x * blockDim.x + threadIdx.x; i < n4; i += stride) {
        float4 r = r4[i];
        unsigned int bx;
        bx = __float_as_uint(r.x);
        if ((bx >> matchShift) == pref) atomicAdd(&sh[(bx >> binShift) & binMask], 1u);
        bx = __float_as_uint(r.y);
        if ((bx >> matchShift) == pref) atomicAdd(&sh[(bx >> binShift) & binMask], 1u);
        bx = __float_as_uint(r.z);
        if ((bx >> matchShift) == pref) atomicAdd(&sh[(bx >> binShift) & binMask], 1u);
        bx = __float_as_uint(r.w);
        if ((bx >> matchShift) == pref) atomicAdd(&sh[(bx >> binShift) & binMask], 1u);
    }
    __syncthreads();
    for (int i = threadIdx.x; i < 2048; i += blockDim.x)
        if (sh[i]) atomicAdd(&g_hist[b][i], sh[i]);
}

// -------------------------- radix select step -------------------------------
__global__ void select_kernel(int bins, int levelBits) {
    int b = blockIdx.x;
    int tid = threadIdx.x;
    long long r = g_rank[b];

    __shared__ long long tsum[TPB];
    __shared__ int s_bin;
    __shared__ long long s_before;

    int per = bins / TPB;      // 8 (2048 bins) or 4 (1024 bins)
    unsigned int c[8];
    long long mysum = 0;
    for (int j = 0; j < per; j++) {
        c[j] = g_hist[b][tid * per + j];
        mysum += (long long)c[j];
    }
    tsum[tid] = mysum;
    __syncthreads();
    // Hillis-Steele inclusive scan over 256 thread sums
    for (int off = 1; off < TPB; off <<= 1) {
        long long v = (tid >= off) ? tsum[tid - off] : 0;
        __syncthreads();
        tsum[tid] += v;
        __syncthreads();
    }
    long long inc = tsum[tid];
    long long base = inc - mysum;
    if (tid == 0) s_bin = -1;
    __syncthreads();

    if (r >= 0 && r >= base && r < inc) {
        long long cum = base;
        for (int j = 0; j < per; j++) {
            if (r < cum + (long long)c[j]) { s_bin = tid * per + j; s_before = cum; break; }
            cum += (long long)c[j];
        }
    }
    __syncthreads();
    if (tid == 0 && s_bin >= 0) {
        g_rank[b]   = r - s_before;
        g_prefix[b] = (g_prefix[b] << levelBits) | (unsigned int)s_bin;
    }
    // zero the histogram for the next level
    for (int i = tid; i < bins; i += TPB) g_hist[b][i] = 0u;
}

// --------------- sum & count of residuals strictly below v ------------------
__global__ void final_kernel(int N) {
    int b = blockIdx.y;
    float v = __uint_as_float(g_prefix[b]);

    int n4 = N >> 2;
    const float4* r4 = reinterpret_cast<const float4*>(g_res) + (size_t)b * n4;
    float s = 0.f;
    long long c = 0;
    int stride = gridDim.x * blockDim.x;
    for (int i = blockIdx.x * blockDim.x + threadIdx.x; i < n4; i += stride) {
        float4 r = r4[i];
        if (r.x < v) { s += r.x; c++; }
        if (r.y < v) { s += r.y; c++; }
        if (r.z < v) { s += r.z; c++; }
        if (r.w < v) { s += r.w; c++; }
    }
    s = warp_sum(s);
    c = warp_sum_ll(c);
    __shared__ float  ws[8];
    __shared__ long long wc[8];
    int lane = threadIdx.x & 31, w = threadIdx.x >> 5;
    if (lane == 0) { ws[w] = s; wc[w] = c; }
    __syncthreads();
    if (w == 0) {
        float a0 = lane < 8 ? ws[lane] : 0.f;
        long long b0 = lane < 8 ? wc[lane] : 0;
        a0 = warp_sum(a0);
        b0 = warp_sum_ll(b0);
        if (lane == 0) {
            atomicAdd(&g_sumless[b], (double)a0);
            atomicAdd(&g_cntless[b], (unsigned long long)b0);
        }
    }
}

// ------------------------------- loss --------------------------------------
__global__ void loss_kernel(float* out) {
    int b = threadIdx.x;
    float loss = 0.f;
    if (b < BB) {
        int k = g_k[b];
        if (k > 0) {
            float v = __uint_as_float(g_prefix[b]);
            double kept = g_sumless[b] +
                          (double)((long long)k - (long long)g_cntless[b]) * (double)v;
            loss = (float)(kept / (double)k);
        }
    }
    #pragma unroll
    for (int off = 16; off; off >>= 1) loss += __shfl_down_sync(0xffffffffu, loss, off);
    if (b == 0) out[0] = loss / (float)BB;
}

// ----------------------------- launch --------------------------------------
extern "C" void kernel_launch(void* const* d_in, const int* in_sizes, int n_in,
                              void* d_out, int out_size) {
    const float* pred = (const float*)d_in[0];
    const float* gt   = (const float*)d_in[1];
    const int*   mask = (const int*)d_in[2];
    float* out = (float*)d_out;

    int total = in_sizes[0];
    int N = total / BB;

    dim3 grid(BLKX, BB);

    init_kernel<<<256, 256>>>();
    moments_kernel<<<grid, TPB>>>(pred, gt, mask, N);
    finalize_moments_kernel<<<1, 32>>>();
    residual_kernel<<<grid, TPB>>>(pred, gt, mask, N);       // + level-0 hist (bits 31..21)
    select_kernel<<<BB, TPB>>>(2048, 11);
    hist_kernel<<<grid, TPB>>>(N, 21, 10, 2047u);            // level-1 (bits 20..10)
    select_kernel<<<BB, TPB>>>(2048, 11);
    hist_kernel<<<grid, TPB>>>(N, 10, 0, 1023u);             // level-2 (bits 9..0)
    select_kernel<<<BB, TPB>>>(1024, 10);
    final_kernel<<<grid, TPB>>>(N);
    loss_kernel<<<1, 32>>>(out);
}